// round 3
// baseline (speedup 1.0000x reference)
#include <cuda_runtime.h>
#include <cuda_bf16.h>
#include <stdint.h>

// loss = 2 - 2 * (sum_i feature[i, label[i]] / SCALE) / n
// feature: [n, C] f32, label: [n] int32, out: scalar f32.
// Single fused launch: gather + per-CTA reduce + last-block global fold.

#define BLOCK 128
#define NBLK_MAX 1024

__device__ float g_partial[NBLK_MAX];
__device__ unsigned int g_count = 0;

__global__ void center_fused_kernel(const float* __restrict__ feature,
                                    const int* __restrict__ label,
                                    float* __restrict__ out,
                                    int n, int C) {
    const int nblocks = gridDim.x;
    int tid = blockIdx.x * BLOCK + threadIdx.x;

    float v = 0.0f;
    if (tid < n) {
        int l = label[tid];
        v = feature[(size_t)tid * (size_t)C + (size_t)l];
    }
    // warp reduce
    #pragma unroll
    for (int off = 16; off > 0; off >>= 1)
        v += __shfl_xor_sync(0xFFFFFFFFu, v, off);

    __shared__ float warp_sums[BLOCK / 32];
    __shared__ bool is_last;
    int wid = threadIdx.x >> 5;
    int lid = threadIdx.x & 31;
    if (lid == 0) warp_sums[wid] = v;
    __syncthreads();

    if (threadIdx.x == 0) {
        float s = 0.0f;
        #pragma unroll
        for (int i = 0; i < BLOCK / 32; i++) s += warp_sums[i];
        g_partial[blockIdx.x] = s;
        __threadfence();                               // partial visible in L2
        unsigned int old = atomicAdd(&g_count, 1u);
        is_last = (old == (unsigned int)(nblocks - 1));
    }
    __syncthreads();

    if (is_last && wid == 0) {
        __threadfence();   // acquire: order partial reads after the count observation
        // fixed-order fold of nblocks partials by one warp (deterministic)
        float s = 0.0f;
        for (int i = lid; i < nblocks; i += 32) s += g_partial[i];
        #pragma unroll
        for (int off = 16; off > 0; off >>= 1)
            s += __shfl_xor_sync(0xFFFFFFFFu, s, off);
        if (lid == 0) {
            out[0] = 2.0f - (2.0f * (s / 64.0f)) / (float)n;
            g_count = 0;   // reset for next graph replay (determinism)
        }
    }
}

extern "C" void kernel_launch(void* const* d_in, const int* in_sizes, int n_in,
                              void* d_out, int out_size) {
    const float* feature = (const float*)d_in[0];
    const int*   label   = (const int*)d_in[1];
    float*       out     = (float*)d_out;

    int n = in_sizes[1];        // 8192
    int C = in_sizes[0] / n;    // 10000

    int nblocks = (n + BLOCK - 1) / BLOCK;   // 64
    if (nblocks > NBLK_MAX) nblocks = NBLK_MAX;

    center_fused_kernel<<<nblocks, BLOCK>>>(feature, label, out, n, C);
}

// round 4
// speedup vs baseline: 1.0295x; 1.0295x over previous
#include <cuda_runtime.h>
#include <cuda_bf16.h>
#include <stdint.h>

// loss = 2 - 2 * (sum_i feature[i, label[i]] / SCALE) / n
// feature: [n, C] f32, label: [n] int32, out: scalar f32.
// Single launch. Hierarchical-counter last-block reduction to avoid the
// ~27cyc/op same-address atomic serialization that killed the R3 version.

#define BLOCK 256
#define MAX_BLOCKS 1024
#define GROUP 8
#define MAX_GROUPS (MAX_BLOCKS / GROUP)

__device__ float        g_partial[MAX_BLOCKS];
__device__ unsigned int g_cnt[MAX_GROUPS];   // zero-initialized at load
__device__ unsigned int g_super = 0;

__global__ void center_fused2_kernel(const float* __restrict__ feature,
                                     const int* __restrict__ label,
                                     float* __restrict__ out,
                                     int n, int C) {
    const int nblocks = gridDim.x;
    const int ngroups = (nblocks + GROUP - 1) / GROUP;
    const int b   = blockIdx.x;
    const int grp = b / GROUP;
    const int grp_size = min(GROUP, nblocks - grp * GROUP);

    int tid = b * BLOCK + threadIdx.x;
    float v = 0.0f;
    if (tid < n) {
        int l = label[tid];
        v = feature[(size_t)tid * (size_t)C + (size_t)l];
    }
    // warp reduce
    #pragma unroll
    for (int off = 16; off > 0; off >>= 1)
        v += __shfl_xor_sync(0xFFFFFFFFu, v, off);

    __shared__ float warp_sums[BLOCK / 32];
    __shared__ int   is_last;
    int wid = threadIdx.x >> 5;
    int lid = threadIdx.x & 31;
    if (lid == 0) warp_sums[wid] = v;
    __syncthreads();

    if (threadIdx.x == 0) {
        float s = 0.0f;
        #pragma unroll
        for (int i = 0; i < BLOCK / 32; i++) s += warp_sums[i];
        g_partial[b] = s;
        __threadfence();   // release: partial visible before counter bump

        int last = 0;
        unsigned int old = atomicAdd(&g_cnt[grp], 1u);
        if (old == (unsigned int)(grp_size - 1)) {
            // last CTA of this group; bump super counter (<= MAX_GROUPS arrivals)
            unsigned int old2 = atomicAdd(&g_super, 1u);
            last = (old2 == (unsigned int)(ngroups - 1));
        }
        is_last = last;
    }
    __syncthreads();

    if (is_last && wid == 0) {
        __threadfence();   // acquire: order partial reads after counter observation
        float s = 0.0f;
        for (int i = lid; i < nblocks; i += 32) s += g_partial[i];
        #pragma unroll
        for (int off = 16; off > 0; off >>= 1)
            s += __shfl_xor_sync(0xFFFFFFFFu, s, off);
        if (lid == 0) {
            out[0] = 2.0f - (2.0f * (s / 64.0f)) / (float)n;
            g_super = 0;   // reset for next graph replay (deterministic state)
        }
        // reset group counters for next replay
        for (int g = lid; g < ngroups; g += 32) g_cnt[g] = 0;
    }
}

extern "C" void kernel_launch(void* const* d_in, const int* in_sizes, int n_in,
                              void* d_out, int out_size) {
    const float* feature = (const float*)d_in[0];
    const int*   label   = (const int*)d_in[1];
    float*       out     = (float*)d_out;

    int n = in_sizes[1];        // 8192
    int C = in_sizes[0] / n;    // 10000

    int nblocks = (n + BLOCK - 1) / BLOCK;   // 32
    if (nblocks > MAX_BLOCKS) nblocks = MAX_BLOCKS;

    center_fused2_kernel<<<nblocks, BLOCK>>>(feature, label, out, n, C);
}

// round 5
// speedup vs baseline: 1.1577x; 1.1245x over previous
#include <cuda_runtime.h>
#include <cuda_bf16.h>
#include <stdint.h>

// loss = 2 - 2 * (sum_i feature[i, label[i]] / SCALE) / n
// feature: [n, C] f32, label: [n] int32, out: scalar f32.
// Single launch, 8-CTA cluster. Cross-CTA handoff via DSMEM + cluster barrier
// (no L2 atomics, no threadfence).

#define CLUSTER 8
#define BLOCK 1024

__global__ void __cluster_dims__(CLUSTER, 1, 1) __launch_bounds__(BLOCK, 1)
center_cluster_kernel(const float* __restrict__ feature,
                      const int* __restrict__ label,
                      float* __restrict__ out,
                      int n, int C) {
    __shared__ float warp_sums[BLOCK / 32];
    __shared__ float cta_slots[CLUSTER];   // only rank 0's copy is read

    uint32_t rank;
    asm("mov.u32 %0, %%cluster_ctarank;" : "=r"(rank));

    const int T = gridDim.x * BLOCK;       // 8192 threads
    int gtid = blockIdx.x * BLOCK + threadIdx.x;

    float v = 0.0f;
    for (int i = gtid; i < n; i += T) {
        int l = label[i];
        v += feature[(size_t)i * (size_t)C + (size_t)l];
    }

    // warp reduce
    #pragma unroll
    for (int off = 16; off > 0; off >>= 1)
        v += __shfl_xor_sync(0xFFFFFFFFu, v, off);

    int wid = threadIdx.x >> 5;
    int lid = threadIdx.x & 31;
    if (lid == 0) warp_sums[wid] = v;
    __syncthreads();

    if (wid == 0) {
        float s = (lid < BLOCK / 32) ? warp_sums[lid] : 0.0f;
        #pragma unroll
        for (int off = 16; off > 0; off >>= 1)
            s += __shfl_xor_sync(0xFFFFFFFFu, s, off);
        if (lid == 0) {
            // store this CTA's partial into rank 0's cta_slots[rank] via DSMEM
            uint32_t laddr;
            asm("{ .reg .u64 t; cvta.to.shared.u64 t, %1; cvt.u32.u64 %0, t; }"
                : "=r"(laddr) : "l"(&cta_slots[rank]));
            uint32_t raddr;
            asm("mapa.shared::cluster.u32 %0, %1, 0;" : "=r"(raddr) : "r"(laddr));
            asm volatile("st.shared::cluster.f32 [%0], %1;"
                         :: "r"(raddr), "f"(s) : "memory");
        }
    }

    // cluster barrier: arrive has release semantics (orders the DSMEM store),
    // wait has acquire semantics (orders rank 0's reads).
    asm volatile("barrier.cluster.arrive.aligned;" ::: "memory");
    asm volatile("barrier.cluster.wait.aligned;" ::: "memory");

    if (rank == 0 && threadIdx.x == 0) {
        float s = 0.0f;
        #pragma unroll
        for (int i = 0; i < CLUSTER; i++) s += cta_slots[i];
        out[0] = 2.0f - (2.0f * (s / 64.0f)) / (float)n;
    }
}

extern "C" void kernel_launch(void* const* d_in, const int* in_sizes, int n_in,
                              void* d_out, int out_size) {
    const float* feature = (const float*)d_in[0];
    const int*   label   = (const int*)d_in[1];
    float*       out     = (float*)d_out;

    int n = in_sizes[1];        // 8192
    int C = in_sizes[0] / n;    // 10000

    center_cluster_kernel<<<CLUSTER, BLOCK>>>(feature, label, out, n, C);
}

// round 6
// speedup vs baseline: 1.2977x; 1.1209x over previous
#include <cuda_runtime.h>
#include <cuda_bf16.h>
#include <stdint.h>

// loss = 2 - 2 * (sum_i feature[i, label[i]] / SCALE) / n
// feature: [n, C] f32, label: [n] int32, out: scalar f32.
// Single classic launch, 64 CTAs. Handoff: each CTA writes (partial, flag)
// as ONE 8-byte word; CTA 0 warp 0 spin-reads the 64 words, folds in fixed
// order, writes out, and clears the flags for the next graph replay.

#define BLOCK 128
#define NBLK 64

__device__ unsigned long long g_slot[NBLK];   // [flag:32 | f32 bits:32], zero-init

__device__ __forceinline__ void st_slot(int i, unsigned long long w) {
    asm volatile("st.relaxed.gpu.global.b64 [%0], %1;"
                 :: "l"(&g_slot[i]), "l"(w) : "memory");
}
__device__ __forceinline__ unsigned long long ld_slot(int i) {
    unsigned long long w;
    asm volatile("ld.relaxed.gpu.global.b64 %0, [%1];"
                 : "=l"(w) : "l"(&g_slot[i]) : "memory");
    return w;
}

__global__ void __launch_bounds__(BLOCK, 1)
center_spin_kernel(const float* __restrict__ feature,
                   const int* __restrict__ label,
                   float* __restrict__ out,
                   int n, int C) {
    const int b = blockIdx.x;
    int tid = b * BLOCK + threadIdx.x;

    float v = 0.0f;
    if (tid < n) {
        int l = label[tid];
        v = feature[(size_t)tid * (size_t)C + (size_t)l];
    }
    // warp reduce
    #pragma unroll
    for (int off = 16; off > 0; off >>= 1)
        v += __shfl_xor_sync(0xFFFFFFFFu, v, off);

    __shared__ float warp_sums[BLOCK / 32];
    int wid = threadIdx.x >> 5;
    int lid = threadIdx.x & 31;
    if (lid == 0) warp_sums[wid] = v;
    __syncthreads();

    if (threadIdx.x == 0) {
        float s = 0.0f;
        #pragma unroll
        for (int i = 0; i < BLOCK / 32; i++) s += warp_sums[i];
        // one 8-byte store carries value + ready flag (atomic by width)
        unsigned long long w =
            ((unsigned long long)1u << 32) | (unsigned long long)__float_as_uint(s);
        st_slot(b, w);
    }

    // CTA 0, warp 0: poll all 64 slots (2 per lane), fold, write, reset.
    if (b == 0 && wid == 0) {
        int i0 = lid, i1 = lid + 32;
        unsigned long long w0, w1;
        do { w0 = ld_slot(i0); } while ((unsigned)(w0 >> 32) == 0u);
        do { w1 = ld_slot(i1); } while ((unsigned)(w1 >> 32) == 0u);

        float s = __uint_as_float((unsigned)w0) + __uint_as_float((unsigned)w1);
        #pragma unroll
        for (int off = 16; off > 0; off >>= 1)
            s += __shfl_xor_sync(0xFFFFFFFFu, s, off);
        if (lid == 0)
            out[0] = 2.0f - (2.0f * (s / 64.0f)) / (float)n;

        // clear flags for the next replay (replays are serialized; all reads done)
        st_slot(i0, 0ull);
        st_slot(i1, 0ull);
    }
}

extern "C" void kernel_launch(void* const* d_in, const int* in_sizes, int n_in,
                              void* d_out, int out_size) {
    const float* feature = (const float*)d_in[0];
    const int*   label   = (const int*)d_in[1];
    float*       out     = (float*)d_out;

    int n = in_sizes[1];        // 8192
    int C = in_sizes[0] / n;    // 10000

    center_spin_kernel<<<NBLK, BLOCK>>>(feature, label, out, n, C);
}

// round 7
// speedup vs baseline: 1.3413x; 1.0337x over previous
#include <cuda_runtime.h>
#include <cuda_bf16.h>
#include <stdint.h>

// loss = 2 - 2 * (sum_i feature[i, label[i]] / SCALE) / n
// feature: [n, C] f32, label: [n] int32, out: scalar f32.
// Single classic launch, 32 CTAs x 256. Each CTA writes (flag|partial) as one
// 8-byte word; CTA 0 warp 0 polls 32 slots (exactly one per lane), folds in
// fixed order, writes out, clears flags for the next graph replay.

#define BLOCK 256
#define NBLK 32

__device__ unsigned long long g_slot[NBLK];   // [flag:32 | f32 bits:32], zero-init

__device__ __forceinline__ void st_slot(int i, unsigned long long w) {
    asm volatile("st.relaxed.gpu.global.b64 [%0], %1;"
                 :: "l"(&g_slot[i]), "l"(w) : "memory");
}
__device__ __forceinline__ unsigned long long ld_slot(int i) {
    unsigned long long w;
    asm volatile("ld.relaxed.gpu.global.b64 %0, [%1];"
                 : "=l"(w) : "l"(&g_slot[i]) : "memory");
    return w;
}

__global__ void __launch_bounds__(BLOCK, 1)
center_spin2_kernel(const float* __restrict__ feature,
                    const int* __restrict__ label,
                    float* __restrict__ out,
                    int n, int C) {
    const int b = blockIdx.x;
    int tid = b * BLOCK + threadIdx.x;

    float v = 0.0f;
    if (tid < n) {
        int l = label[tid];
        v = feature[(size_t)tid * (size_t)C + (size_t)l];
    }
    // warp reduce
    #pragma unroll
    for (int off = 16; off > 0; off >>= 1)
        v += __shfl_xor_sync(0xFFFFFFFFu, v, off);

    __shared__ float warp_sums[BLOCK / 32];
    int wid = threadIdx.x >> 5;
    int lid = threadIdx.x & 31;
    if (lid == 0) warp_sums[wid] = v;
    __syncthreads();

    if (threadIdx.x == 0) {
        float s = 0.0f;
        #pragma unroll
        for (int i = 0; i < BLOCK / 32; i++) s += warp_sums[i];
        unsigned long long w =
            ((unsigned long long)1u << 32) | (unsigned long long)__float_as_uint(s);
        st_slot(b, w);
    }

    // CTA 0, warp 0: one slot per lane, single poll loop, fold, write, reset.
    if (b == 0 && wid == 0) {
        unsigned long long w;
        do { w = ld_slot(lid); } while ((unsigned)(w >> 32) == 0u);

        float s = __uint_as_float((unsigned)w);
        #pragma unroll
        for (int off = 16; off > 0; off >>= 1)
            s += __shfl_xor_sync(0xFFFFFFFFu, s, off);
        if (lid == 0)
            out[0] = 2.0f - (2.0f * (s / 64.0f)) / (float)n;

        // clear flag for the next replay (replays serialized; all reads done)
        st_slot(lid, 0ull);
    }
}

extern "C" void kernel_launch(void* const* d_in, const int* in_sizes, int n_in,
                              void* d_out, int out_size) {
    const float* feature = (const float*)d_in[0];
    const int*   label   = (const int*)d_in[1];
    float*       out     = (float*)d_out;

    int n = in_sizes[1];        // 8192
    int C = in_sizes[0] / n;    // 10000

    center_spin2_kernel<<<NBLK, BLOCK>>>(feature, label, out, n, C);
}